// round 1
// baseline (speedup 1.0000x reference)
#include <cuda_runtime.h>

#define B_   2
#define S_   2048
#define D_   1024
#define H_   16
#define HD_  64
#define MTOT (B_ * S_)   // 4096 rows total across batch

// ---------------------------------------------------------------------------
// Device scratch (static allocation — no cudaMalloc allowed)
// ---------------------------------------------------------------------------
__device__ float g_Q[MTOT * D_];
__device__ float g_K[MTOT * D_];
__device__ float g_V[MTOT * D_];
__device__ float g_A[MTOT * D_];   // attention output in the "mis-reshaped" layout

// ---------------------------------------------------------------------------
// 128x128x16 register-tiled SGEMM body: C[M,N] = A[M,K] @ W[K,N] (+ bias)
// 256 threads, 8x8 accumulators per thread.
// ---------------------------------------------------------------------------
__device__ __forceinline__ void sgemm_body(
    const float* __restrict__ A, const float* __restrict__ W,
    const float* __restrict__ bias, float* __restrict__ C,
    int M, int N, int K)
{
    __shared__ float As[16][128];   // transposed A tile: As[k][m]
    __shared__ float Bs[16][128];   // Bs[k][n]

    const int tid  = threadIdx.x;
    const int tx   = tid & 15;          // N sub-tile (8 cols)
    const int ty   = tid >> 4;          // M sub-tile (8 rows)
    const int arow = tid >> 2;          // 0..63
    const int acol = (tid & 3) << 2;    // 0,4,8,12
    const int brow = tid >> 5;          // 0..7
    const int bcol = (tid & 31) << 2;   // 0..124

    const float* Ab = A + (size_t)(blockIdx.y * 128) * K;
    const float* Wb = W + blockIdx.x * 128;

    float acc[8][8];
#pragma unroll
    for (int i = 0; i < 8; i++)
#pragma unroll
        for (int j = 0; j < 8; j++) acc[i][j] = 0.f;

    for (int k0 = 0; k0 < K; k0 += 16) {
        float4 a0 = *(const float4*)(Ab + (size_t)arow * K        + k0 + acol);
        float4 a1 = *(const float4*)(Ab + (size_t)(arow + 64) * K + k0 + acol);
        float4 b0 = *(const float4*)(Wb + (size_t)(k0 + brow)     * N + bcol);
        float4 b1 = *(const float4*)(Wb + (size_t)(k0 + brow + 8) * N + bcol);

        __syncthreads();   // previous iteration's readers done

        As[acol + 0][arow]      = a0.x; As[acol + 1][arow]      = a0.y;
        As[acol + 2][arow]      = a0.z; As[acol + 3][arow]      = a0.w;
        As[acol + 0][arow + 64] = a1.x; As[acol + 1][arow + 64] = a1.y;
        As[acol + 2][arow + 64] = a1.z; As[acol + 3][arow + 64] = a1.w;
        *(float4*)&Bs[brow][bcol]     = b0;
        *(float4*)&Bs[brow + 8][bcol] = b1;

        __syncthreads();

#pragma unroll
        for (int kk = 0; kk < 16; kk++) {
            float ar[8], br[8];
            *(float4*)&ar[0] = *(const float4*)&As[kk][ty * 8];
            *(float4*)&ar[4] = *(const float4*)&As[kk][ty * 8 + 4];
            *(float4*)&br[0] = *(const float4*)&Bs[kk][tx * 8];
            *(float4*)&br[4] = *(const float4*)&Bs[kk][tx * 8 + 4];
#pragma unroll
            for (int i = 0; i < 8; i++)
#pragma unroll
                for (int j = 0; j < 8; j++)
                    acc[i][j] += ar[i] * br[j];
        }
    }

    float bv[8];
#pragma unroll
    for (int j = 0; j < 8; j++)
        bv[j] = bias ? bias[blockIdx.x * 128 + tx * 8 + j] : 0.f;

#pragma unroll
    for (int i = 0; i < 8; i++) {
        const int row = blockIdx.y * 128 + ty * 8 + i;
        float* Cp = C + (size_t)row * N + blockIdx.x * 128 + tx * 8;
        float4 o0 = make_float4(acc[i][0] + bv[0], acc[i][1] + bv[1],
                                acc[i][2] + bv[2], acc[i][3] + bv[3]);
        float4 o1 = make_float4(acc[i][4] + bv[4], acc[i][5] + bv[5],
                                acc[i][6] + bv[6], acc[i][7] + bv[7]);
        *(float4*)(Cp)     = o0;
        *(float4*)(Cp + 4) = o1;
    }
}

// QKV projection: grid.z selects which weight / output
__global__ void __launch_bounds__(256)
qkv_gemm_kernel(const float* __restrict__ x,
                const float* __restrict__ Wq,
                const float* __restrict__ Wk,
                const float* __restrict__ Wv)
{
    const float* W = (blockIdx.z == 0) ? Wq : ((blockIdx.z == 1) ? Wk : Wv);
    float* out     = (blockIdx.z == 0) ? g_Q : ((blockIdx.z == 1) ? g_K : g_V);
    sgemm_body(x, W, nullptr, out, MTOT, D_, D_);
}

// Output projection: g_A @ Wo + bo -> d_out
__global__ void __launch_bounds__(256)
out_gemm_kernel(const float* __restrict__ Wo,
                const float* __restrict__ bo,
                float* __restrict__ out)
{
    sgemm_body(g_A, Wo, bo, out, MTOT, D_, D_);
}

// ---------------------------------------------------------------------------
// Causal flash attention (fp32). One CTA = (batch b, head h, 128 q-rows).
// One thread per q row; q & acc live in registers; K/V 64x64 tiles in SMEM.
// Writes the result directly in the reference's "no head-transpose" reshape:
//   out[b, h*128 + s/16, (s%16)*64 + d] = attn[b,h,s,d]
// ---------------------------------------------------------------------------
__global__ void __launch_bounds__(128)
flash_attn_kernel()
{
    const int qb  = blockIdx.x;     // 0..15 (128 q rows each)
    const int h   = blockIdx.y;     // 0..15
    const int b   = blockIdx.z;     // 0..1
    const int tid = threadIdx.x;    // 128 threads
    const int qi  = qb * 128 + tid; // this thread's query row (s index)

    __shared__ float Ks[64][64];
    __shared__ float Vs[64][64];

    float4 q[16], acc[16];
    const float* Qp = g_Q + ((size_t)(b * S_ + qi)) * D_ + h * HD_;
#pragma unroll
    for (int i = 0; i < 16; i++) {
        q[i]   = *(const float4*)(Qp + i * 4);
        acc[i] = make_float4(0.f, 0.f, 0.f, 0.f);
    }
    float m = -1e30f, l = 0.f;

    const int r  = tid >> 1;          // kv row this thread loads (2 thr/row)
    const int cp = (tid & 1) * 32;    // column half

    const int ntiles = qb * 2 + 2;    // causal: only tiles touching <= diag
    for (int t = 0; t < ntiles; t++) {
        const int kv0 = t * 64;
        const float* Kp = g_K + ((size_t)(b * S_ + kv0 + r)) * D_ + h * HD_ + cp;
        const float* Vp = g_V + ((size_t)(b * S_ + kv0 + r)) * D_ + h * HD_ + cp;

        __syncthreads();
#pragma unroll
        for (int i = 0; i < 8; i++) {
            *(float4*)&Ks[r][cp + i * 4] = *(const float4*)(Kp + i * 4);
            *(float4*)&Vs[r][cp + i * 4] = *(const float4*)(Vp + i * 4);
        }
        __syncthreads();

        int jmax = qi - kv0 + 1;
        if (jmax > 64) jmax = 64;
        for (int j = 0; j < jmax; j++) {
            const float4* kr = (const float4*)&Ks[j][0];   // broadcast reads
            float s = 0.f;
#pragma unroll
            for (int i = 0; i < 16; i++) {
                float4 kv = kr[i];
                s += q[i].x * kv.x + q[i].y * kv.y + q[i].z * kv.z + q[i].w * kv.w;
            }
            s *= 0.125f;   // 1/sqrt(64)

            if (s > m) {   // rare rescale path
                const float al = __expf(m - s);
                l *= al;
#pragma unroll
                for (int i = 0; i < 16; i++) {
                    acc[i].x *= al; acc[i].y *= al; acc[i].z *= al; acc[i].w *= al;
                }
                m = s;
            }
            const float p = __expf(s - m);
            l += p;
            const float4* vr = (const float4*)&Vs[j][0];
#pragma unroll
            for (int i = 0; i < 16; i++) {
                float4 vv = vr[i];
                acc[i].x += p * vv.x; acc[i].y += p * vv.y;
                acc[i].z += p * vv.z; acc[i].w += p * vv.w;
            }
        }
    }

    const float inv = 1.f / l;
    // mis-reshape: row = h*128 + s/16, col = (s%16)*64 + d
    const int rrow = h * 128 + (qi >> 4);
    const int ccol = (qi & 15) * 64;
    float* Op = g_A + ((size_t)(b * S_ + rrow)) * D_ + ccol;
#pragma unroll
    for (int i = 0; i < 16; i++) {
        float4 o = make_float4(acc[i].x * inv, acc[i].y * inv,
                               acc[i].z * inv, acc[i].w * inv);
        *(float4*)(Op + i * 4) = o;
    }
}

// ---------------------------------------------------------------------------
// Launch
// ---------------------------------------------------------------------------
extern "C" void kernel_launch(void* const* d_in, const int* in_sizes, int n_in,
                              void* d_out, int out_size)
{
    const float* x  = (const float*)d_in[0];
    const float* Wq = (const float*)d_in[1];
    const float* Wk = (const float*)d_in[2];
    const float* Wv = (const float*)d_in[3];
    const float* Wo = (const float*)d_in[4];
    const float* bo = (const float*)d_in[5];
    float* out = (float*)d_out;

    dim3 blk(256);
    dim3 g_qkv(D_ / 128, MTOT / 128, 3);          // 8 x 32 x 3
    qkv_gemm_kernel<<<g_qkv, blk>>>(x, Wq, Wk, Wv);

    dim3 g_attn(S_ / 128, H_, B_);                // 16 x 16 x 2
    flash_attn_kernel<<<g_attn, 128>>>();

    dim3 g_out(D_ / 128, MTOT / 128, 1);          // 8 x 32
    out_gemm_kernel<<<g_out, blk>>>(Wo, bo, out);
}

// round 6
// speedup vs baseline: 1.3036x; 1.3036x over previous
#include <cuda_runtime.h>
#include <cuda_bf16.h>
#include <cstdint>

#define B_   2
#define S_   2048
#define D_   1024
#define H_   16
#define HD_  64
#define MTOT (B_ * S_)   // 4096
#define DD   (D_ * D_)

// ---------------------------------------------------------------------------
// Device scratch (static — no cudaMalloc allowed)
// ---------------------------------------------------------------------------
__device__ float g_Q[MTOT * D_];
__device__ float g_K[MTOT * D_];
__device__ float g_V[MTOT * D_];
__device__ float g_A[MTOT * D_];                 // attention out, mis-reshaped
__device__ __nv_bfloat16 g_xhi[MTOT * D_], g_xlo[MTOT * D_];
__device__ __nv_bfloat16 g_ahi[MTOT * D_], g_alo[MTOT * D_];
__device__ __nv_bfloat16 g_wThi[4 * DD],   g_wTlo[4 * DD];   // W^T [n][k]

// ---------------------------------------------------------------------------
// PTX helpers (sm_80+ only: cp.async, ldmatrix, mma.sync — no tcgen05)
// ---------------------------------------------------------------------------
__device__ __forceinline__ uint32_t smem_u32(const void* p) {
    uint32_t a;
    asm("{ .reg .u64 t; cvta.to.shared.u64 t, %1; cvt.u32.u64 %0, t; }"
        : "=r"(a) : "l"(p));
    return a;
}
__device__ __forceinline__ void cp16(uint32_t d, const void* s) {
    asm volatile("cp.async.cg.shared.global [%0], [%1], 16;" :: "r"(d), "l"(s));
}
#define CP_COMMIT() asm volatile("cp.async.commit_group;")
#define CP_WAIT1()  asm volatile("cp.async.wait_group 1;")
#define CP_WAIT0()  asm volatile("cp.async.wait_group 0;")

__device__ __forceinline__ void ldmA(uint32_t* r, uint32_t a) {
    asm volatile("ldmatrix.sync.aligned.m8n8.x4.shared.b16 {%0,%1,%2,%3}, [%4];"
                 : "=r"(r[0]), "=r"(r[1]), "=r"(r[2]), "=r"(r[3]) : "r"(a));
}
__device__ __forceinline__ void ldmB(uint32_t* r, uint32_t a) {
    asm volatile("ldmatrix.sync.aligned.m8n8.x2.shared.b16 {%0,%1}, [%2];"
                 : "=r"(r[0]), "=r"(r[1]) : "r"(a));
}
__device__ __forceinline__ void hmma(float* c, const uint32_t* a, const uint32_t* b) {
    asm volatile(
        "mma.sync.aligned.m16n8k16.row.col.f32.bf16.bf16.f32 "
        "{%0,%1,%2,%3}, {%4,%5,%6,%7}, {%8,%9}, {%0,%1,%2,%3};"
        : "+f"(c[0]), "+f"(c[1]), "+f"(c[2]), "+f"(c[3])
        : "r"(a[0]), "r"(a[1]), "r"(a[2]), "r"(a[3]), "r"(b[0]), "r"(b[1]));
}

// ---------------------------------------------------------------------------
// fp32 -> (bf16 hi, bf16 lo) split + conversion kernels
// ---------------------------------------------------------------------------
__device__ __forceinline__ void split1(float v, __nv_bfloat16& h, __nv_bfloat16& l) {
    h = __float2bfloat16(v);
    l = __float2bfloat16(v - __bfloat162float(h));
}

__global__ void __launch_bounds__(256)
conv_x_kernel(const float* __restrict__ in, int which)   // 0 -> x, 1 -> g_A
{
    const float* src = which ? g_A : in;
    __nv_bfloat16* hi = which ? g_ahi : g_xhi;
    __nv_bfloat16* lo = which ? g_alo : g_xlo;
    int i = blockIdx.x * 256 + threadIdx.x;
    float4 v = ((const float4*)src)[i];
    __nv_bfloat16 h0, h1, h2, h3, l0, l1, l2, l3;
    split1(v.x, h0, l0); split1(v.y, h1, l1);
    split1(v.z, h2, l2); split1(v.w, h3, l3);
    ((__nv_bfloat162*)hi)[2 * i]     = __nv_bfloat162(h0, h1);
    ((__nv_bfloat162*)hi)[2 * i + 1] = __nv_bfloat162(h2, h3);
    ((__nv_bfloat162*)lo)[2 * i]     = __nv_bfloat162(l0, l1);
    ((__nv_bfloat162*)lo)[2 * i + 1] = __nv_bfloat162(l2, l3);
}

__global__ void __launch_bounds__(256)
conv_wT_kernel(const float* __restrict__ Wq, const float* __restrict__ Wk,
               const float* __restrict__ Wv, const float* __restrict__ Wo)
{
    const float* W = (blockIdx.z == 0) ? Wq : (blockIdx.z == 1) ? Wk
                    : (blockIdx.z == 2) ? Wv : Wo;
    __nv_bfloat16* Hi = g_wThi + (size_t)blockIdx.z * DD;
    __nv_bfloat16* Lo = g_wTlo + (size_t)blockIdx.z * DD;

    __shared__ float tile[32][33];
    const int tx = threadIdx.x & 31, ty = threadIdx.x >> 5;
    const int n0 = blockIdx.x * 32, k0 = blockIdx.y * 32;
#pragma unroll
    for (int i = 0; i < 4; i++)
        tile[ty + 8 * i][tx] = W[(size_t)(k0 + ty + 8 * i) * D_ + n0 + tx];
    __syncthreads();
#pragma unroll
    for (int i = 0; i < 4; i++) {
        float v = tile[tx][ty + 8 * i];
        __nv_bfloat16 h, l; split1(v, h, l);
        size_t o = (size_t)(n0 + ty + 8 * i) * D_ + k0 + tx;
        Hi[o] = h; Lo[o] = l;
    }
}

// ---------------------------------------------------------------------------
// HMMA bf16x3 GEMM: C[128x128 tile] = A[M,1024] @ B^T  (B stored [n][k])
// 8 warps (2m x 4n), warp tile 64x32, K-chunk 32, cp.async double buffer.
// SMEM rows padded to 40 bf16 (80B) -> conflict-free ldmatrix.
// ---------------------------------------------------------------------------
#define KCH   32
#define NCH   (D_ / KCH)        // 32
#define LDKB  80                // bytes per padded row
#define T_A_HI 0
#define T_A_LO 10240
#define T_B_HI 20480
#define T_B_LO 30720
#define STAGE  40960
#define GSMEM  (2 * STAGE)

__device__ __forceinline__ void hmma_gemm_body(
    const __nv_bfloat16* __restrict__ Ahi, const __nv_bfloat16* __restrict__ Alo,
    const __nv_bfloat16* __restrict__ Bhi, const __nv_bfloat16* __restrict__ Blo,
    float* __restrict__ C, const float* __restrict__ bias)
{
    extern __shared__ char sm[];
    const uint32_t sb = smem_u32(sm);
    const int tid  = threadIdx.x;
    const int lane = tid & 31;
    const int wid  = tid >> 5;
    const int wm   = (wid & 1) * 64;     // warp m offset in tile
    const int wn   = (wid >> 1) * 32;    // warp n offset in tile
    const int m0   = blockIdx.y * 128;
    const int n0   = blockIdx.x * 128;

    // per-thread gmem/smem load mapping: 2 x 16B per tensor per chunk
    const int r0 = tid >> 1;             // rows handled: r0, r0+? -> idx scheme
    // idx = tid + t*256 ; row = idx>>2 ; q = idx&3
    // ldmatrix per-lane offsets
    const uint32_t aoff = (uint32_t)((wm + (lane & 15)) * LDKB + (lane >> 4) * 16);
    const uint32_t boff = (uint32_t)((wn + (lane & 7))  * LDKB + ((lane >> 3) & 1) * 16);

    float acc[4][4][4];
#pragma unroll
    for (int i = 0; i < 4; i++)
#pragma unroll
        for (int j = 0; j < 4; j++)
#pragma unroll
            for (int q = 0; q < 4; q++) acc[i][j][q] = 0.f;

    // ---- load one chunk's 4 tensors into stage s
    auto issue = [&](int c, int s) {
        const int k0 = c * KCH;
        const uint32_t st = sb + s * STAGE;
#pragma unroll
        for (int t = 0; t < 2; t++) {
            int idx = tid + t * 256;
            int row = idx >> 2, q = idx & 3;
            uint32_t so = (uint32_t)(row * LDKB + q * 16);
            const size_t ga = (size_t)(m0 + row) * D_ + k0 + q * 8;
            const size_t gb = (size_t)(n0 + row) * D_ + k0 + q * 8;
            cp16(st + T_A_HI + so, Ahi + ga);
            cp16(st + T_A_LO + so, Alo + ga);
            cp16(st + T_B_HI + so, Bhi + gb);
            cp16(st + T_B_LO + so, Blo + gb);
        }
        CP_COMMIT();
    };

    issue(0, 0);
    for (int c = 0; c < NCH; ++c) {
        const int s = c & 1;
        if (c + 1 < NCH) { issue(c + 1, s ^ 1); CP_WAIT1(); }
        else             { CP_WAIT0(); }
        __syncthreads();

        const uint32_t st = sb + s * STAGE;
        const uint32_t ah_b = st + T_A_HI + aoff;
        const uint32_t al_b = st + T_A_LO + aoff;
        const uint32_t bh_b = st + T_B_HI + boff;
        const uint32_t bl_b = st + T_B_LO + boff;

#pragma unroll
        for (int ks = 0; ks < 2; ks++) {
            const uint32_t ko = ks * 32;   // 16 bf16 = 32B
            uint32_t ah[4][4], al[4][4], bh[4][2], bl[4][2];
#pragma unroll
            for (int i = 0; i < 4; i++) {
                ldmA(ah[i], ah_b + ko + i * (16 * LDKB));
                ldmA(al[i], al_b + ko + i * (16 * LDKB));
            }
#pragma unroll
            for (int j = 0; j < 4; j++) {
                ldmB(bh[j], bh_b + ko + j * (8 * LDKB));
                ldmB(bl[j], bl_b + ko + j * (8 * LDKB));
            }
#pragma unroll
            for (int i = 0; i < 4; i++)
#pragma unroll
                for (int j = 0; j < 4; j++) hmma(acc[i][j], ah[i], bh[j]);
#pragma unroll
            for (int i = 0; i < 4; i++)
#pragma unroll
                for (int j = 0; j < 4; j++) hmma(acc[i][j], ah[i], bl[j]);
#pragma unroll
            for (int i = 0; i < 4; i++)
#pragma unroll
                for (int j = 0; j < 4; j++) hmma(acc[i][j], al[i], bh[j]);
        }
        __syncthreads();
    }

    // ---- epilogue: c0,c1 -> (m=gid, n=tig*2); c2,c3 -> m+8
    const int gid = lane >> 2, tig = lane & 3;
#pragma unroll
    for (int i = 0; i < 4; i++) {
        const int row = m0 + wm + i * 16 + gid;
#pragma unroll
        for (int j = 0; j < 4; j++) {
            const int col = n0 + wn + j * 8 + tig * 2;
            float b0 = 0.f, b1 = 0.f;
            if (bias) { b0 = bias[col]; b1 = bias[col + 1]; }
            *(float2*)(C + (size_t)row * D_ + col) =
                make_float2(acc[i][j][0] + b0, acc[i][j][1] + b1);
            *(float2*)(C + (size_t)(row + 8) * D_ + col) =
                make_float2(acc[i][j][2] + b0, acc[i][j][3] + b1);
        }
    }
    (void)r0;
}

__global__ void __launch_bounds__(256, 1)
hmma_qkv_kernel()
{
    const __nv_bfloat16* Bh = g_wThi + (size_t)blockIdx.z * DD;
    const __nv_bfloat16* Bl = g_wTlo + (size_t)blockIdx.z * DD;
    float* C = (blockIdx.z == 0) ? g_Q : (blockIdx.z == 1) ? g_K : g_V;
    hmma_gemm_body(g_xhi, g_xlo, Bh, Bl, C, nullptr);
}

__global__ void __launch_bounds__(256, 1)
hmma_out_kernel(const float* __restrict__ bo, float* __restrict__ out)
{
    hmma_gemm_body(g_ahi, g_alo, g_wThi + 3ull * DD, g_wTlo + 3ull * DD, out, bo);
}

// ---------------------------------------------------------------------------
// Causal flash attention (fp32) — unchanged from R1 (proven).
// ---------------------------------------------------------------------------
__global__ void __launch_bounds__(128)
flash_attn_kernel()
{
    const int qb  = blockIdx.x;
    const int h   = blockIdx.y;
    const int b   = blockIdx.z;
    const int tid = threadIdx.x;
    const int qi  = qb * 128 + tid;

    __shared__ float Ks[64][64];
    __shared__ float Vs[64][64];

    float4 q[16], acc[16];
    const float* Qp = g_Q + ((size_t)(b * S_ + qi)) * D_ + h * HD_;
#pragma unroll
    for (int i = 0; i < 16; i++) {
        q[i]   = *(const float4*)(Qp + i * 4);
        acc[i] = make_float4(0.f, 0.f, 0.f, 0.f);
    }
    float m = -1e30f, l = 0.f;

    const int r  = tid >> 1;
    const int cp = (tid & 1) * 32;

    const int ntiles = qb * 2 + 2;
    for (int t = 0; t < ntiles; t++) {
        const int kv0 = t * 64;
        const float* Kp = g_K + ((size_t)(b * S_ + kv0 + r)) * D_ + h * HD_ + cp;
        const float* Vp = g_V + ((size_t)(b * S_ + kv0 + r)) * D_ + h * HD_ + cp;

        __syncthreads();
#pragma unroll
        for (int i = 0; i < 8; i++) {
            *(float4*)&Ks[r][cp + i * 4] = *(const float4*)(Kp + i * 4);
            *(float4*)&Vs[r][cp + i * 4] = *(const float4*)(Vp + i * 4);
        }
        __syncthreads();

        int jmax = qi - kv0 + 1;
        if (jmax > 64) jmax = 64;
        for (int j = 0; j < jmax; j++) {
            const float4* kr = (const float4*)&Ks[j][0];
            float s = 0.f;
#pragma unroll
            for (int i = 0; i < 16; i++) {
                float4 kv = kr[i];
                s += q[i].x * kv.x + q[i].y * kv.y + q[i].z * kv.z + q[i].w * kv.w;
            }
            s *= 0.125f;

            if (s > m) {
                const float al = __expf(m - s);
                l *= al;
#pragma unroll
                for (int i = 0; i < 16; i++) {
                    acc[i].x *= al; acc[i].y *= al; acc[i].z *= al; acc[i].w *= al;
                }
                m = s;
            }
            const float p = __expf(s - m);
            l += p;
            const float4* vr = (const float4*)&Vs[j][0];
#pragma unroll
            for (int i = 0; i < 16; i++) {
                float4 vv = vr[i];
                acc[i].x += p * vv.x; acc[i].y += p * vv.y;
                acc[i].z += p * vv.z; acc[i].w += p * vv.w;
            }
        }
    }

    const float inv = 1.f / l;
    const int rrow = h * 128 + (qi >> 4);
    const int ccol = (qi & 15) * 64;
    float* Op = g_A + ((size_t)(b * S_ + rrow)) * D_ + ccol;
#pragma unroll
    for (int i = 0; i < 16; i++) {
        float4 o = make_float4(acc[i].x * inv, acc[i].y * inv,
                               acc[i].z * inv, acc[i].w * inv);
        *(float4*)(Op + i * 4) = o;
    }
}

// ---------------------------------------------------------------------------
// Launch
// ---------------------------------------------------------------------------
extern "C" void kernel_launch(void* const* d_in, const int* in_sizes, int n_in,
                              void* d_out, int out_size)
{
    const float* x  = (const float*)d_in[0];
    const float* Wq = (const float*)d_in[1];
    const float* Wk = (const float*)d_in[2];
    const float* Wv = (const float*)d_in[3];
    const float* Wo = (const float*)d_in[4];
    const float* bo = (const float*)d_in[5];
    float* out = (float*)d_out;

    cudaFuncSetAttribute(hmma_qkv_kernel,
                         cudaFuncAttributeMaxDynamicSharedMemorySize, GSMEM);
    cudaFuncSetAttribute(hmma_out_kernel,
                         cudaFuncAttributeMaxDynamicSharedMemorySize, GSMEM);

    const int n4 = MTOT * D_ / 4;

    conv_x_kernel<<<n4 / 256, 256>>>(x, 0);
    conv_wT_kernel<<<dim3(32, 32, 4), 256>>>(Wq, Wk, Wv, Wo);

    hmma_qkv_kernel<<<dim3(D_ / 128, MTOT / 128, 3), 256, GSMEM>>>();

    flash_attn_kernel<<<dim3(S_ / 128, H_, B_), 128>>>();

    conv_x_kernel<<<n4 / 256, 256>>>(nullptr, 1);
    hmma_out_kernel<<<dim3(D_ / 128, MTOT / 128, 1), 256, GSMEM>>>(bo, out);
}

// round 7
// speedup vs baseline: 3.1000x; 2.3780x over previous
#include <cuda_runtime.h>
#include <cuda_bf16.h>
#include <cstdint>

#define B_   2
#define S_   2048
#define D_   1024
#define H_   16
#define HD_  64
#define MTOT (B_ * S_)   // 4096
#define DD   (D_ * D_)

// ---------------------------------------------------------------------------
// Device scratch (static — no cudaMalloc allowed). All bf16 hi/lo pairs.
// ---------------------------------------------------------------------------
__device__ __nv_bfloat16 g_xhi[MTOT * D_], g_xlo[MTOT * D_];
__device__ __nv_bfloat16 g_qhi[MTOT * D_], g_qlo[MTOT * D_];
__device__ __nv_bfloat16 g_khi[MTOT * D_], g_klo[MTOT * D_];
__device__ __nv_bfloat16 g_vhi[MTOT * D_], g_vlo[MTOT * D_];
__device__ __nv_bfloat16 g_ahi[MTOT * D_], g_alo[MTOT * D_];
__device__ __nv_bfloat16 g_wThi[4 * DD],   g_wTlo[4 * DD];   // W^T [n][k]

// ---------------------------------------------------------------------------
// PTX helpers (sm_80+ only: cp.async, ldmatrix, mma.sync)
// ---------------------------------------------------------------------------
__device__ __forceinline__ uint32_t smem_u32(const void* p) {
    uint32_t a;
    asm("{ .reg .u64 t; cvta.to.shared.u64 t, %1; cvt.u32.u64 %0, t; }"
        : "=r"(a) : "l"(p));
    return a;
}
__device__ __forceinline__ void cp16(uint32_t d, const void* s) {
    asm volatile("cp.async.cg.shared.global [%0], [%1], 16;" :: "r"(d), "l"(s));
}
#define CP_COMMIT() asm volatile("cp.async.commit_group;")
#define CP_WAIT1()  asm volatile("cp.async.wait_group 1;")
#define CP_WAIT0()  asm volatile("cp.async.wait_group 0;")

__device__ __forceinline__ void ldmA(uint32_t* r, uint32_t a) {
    asm volatile("ldmatrix.sync.aligned.m8n8.x4.shared.b16 {%0,%1,%2,%3}, [%4];"
                 : "=r"(r[0]), "=r"(r[1]), "=r"(r[2]), "=r"(r[3]) : "r"(a));
}
__device__ __forceinline__ void ldmB(uint32_t* r, uint32_t a) {
    asm volatile("ldmatrix.sync.aligned.m8n8.x2.shared.b16 {%0,%1}, [%2];"
                 : "=r"(r[0]), "=r"(r[1]) : "r"(a));
}
__device__ __forceinline__ void ldmBT(uint32_t* r, uint32_t a) {
    asm volatile("ldmatrix.sync.aligned.m8n8.x2.trans.shared.b16 {%0,%1}, [%2];"
                 : "=r"(r[0]), "=r"(r[1]) : "r"(a));
}
__device__ __forceinline__ void hmma(float* c, const uint32_t* a, const uint32_t* b) {
    asm volatile(
        "mma.sync.aligned.m16n8k16.row.col.f32.bf16.bf16.f32 "
        "{%0,%1,%2,%3}, {%4,%5,%6,%7}, {%8,%9}, {%0,%1,%2,%3};"
        : "+f"(c[0]), "+f"(c[1]), "+f"(c[2]), "+f"(c[3])
        : "r"(a[0]), "r"(a[1]), "r"(a[2]), "r"(a[3]), "r"(b[0]), "r"(b[1]));
}
__device__ __forceinline__ float ex2(float x) {
    float r; asm("ex2.approx.ftz.f32 %0, %1;" : "=f"(r) : "f"(x)); return r;
}
__device__ __forceinline__ float qmax(float v) {
    v = fmaxf(v, __shfl_xor_sync(0xFFFFFFFFu, v, 1));
    v = fmaxf(v, __shfl_xor_sync(0xFFFFFFFFu, v, 2));
    return v;
}
__device__ __forceinline__ float qsum(float v) {
    v += __shfl_xor_sync(0xFFFFFFFFu, v, 1);
    v += __shfl_xor_sync(0xFFFFFFFFu, v, 2);
    return v;
}
__device__ __forceinline__ uint32_t packbf(float a, float b) {
    __nv_bfloat162 t = __floats2bfloat162_rn(a, b);
    return *(uint32_t*)&t;
}
__device__ __forceinline__ void split1(float v, __nv_bfloat16& h, __nv_bfloat16& l) {
    h = __float2bfloat16(v);
    l = __float2bfloat16(v - __bfloat162float(h));
}

// ---------------------------------------------------------------------------
// Conversion kernels
// ---------------------------------------------------------------------------
__global__ void __launch_bounds__(256)
conv_x_kernel(const float* __restrict__ in)
{
    int i = blockIdx.x * 256 + threadIdx.x;
    float4 v = ((const float4*)in)[i];
    __nv_bfloat16 h0, h1, h2, h3, l0, l1, l2, l3;
    split1(v.x, h0, l0); split1(v.y, h1, l1);
    split1(v.z, h2, l2); split1(v.w, h3, l3);
    ((__nv_bfloat162*)g_xhi)[2 * i]     = __nv_bfloat162(h0, h1);
    ((__nv_bfloat162*)g_xhi)[2 * i + 1] = __nv_bfloat162(h2, h3);
    ((__nv_bfloat162*)g_xlo)[2 * i]     = __nv_bfloat162(l0, l1);
    ((__nv_bfloat162*)g_xlo)[2 * i + 1] = __nv_bfloat162(l2, l3);
}

__global__ void __launch_bounds__(256)
conv_wT_kernel(const float* __restrict__ Wq, const float* __restrict__ Wk,
               const float* __restrict__ Wv, const float* __restrict__ Wo)
{
    const float* W = (blockIdx.z == 0) ? Wq : (blockIdx.z == 1) ? Wk
                    : (blockIdx.z == 2) ? Wv : Wo;
    __nv_bfloat16* Hi = g_wThi + (size_t)blockIdx.z * DD;
    __nv_bfloat16* Lo = g_wTlo + (size_t)blockIdx.z * DD;

    __shared__ float tile[32][33];
    const int tx = threadIdx.x & 31, ty = threadIdx.x >> 5;
    const int n0 = blockIdx.x * 32, k0 = blockIdx.y * 32;
#pragma unroll
    for (int i = 0; i < 4; i++)
        tile[ty + 8 * i][tx] = W[(size_t)(k0 + ty + 8 * i) * D_ + n0 + tx];
    __syncthreads();
#pragma unroll
    for (int i = 0; i < 4; i++) {
        float v = tile[tx][ty + 8 * i];
        __nv_bfloat16 h, l; split1(v, h, l);
        size_t o = (size_t)(n0 + ty + 8 * i) * D_ + k0 + tx;
        Hi[o] = h; Lo[o] = l;
    }
}

// ---------------------------------------------------------------------------
// HMMA bf16x3 GEMM (as R6), epilogue writes EITHER fp32 C+bias OR bf16 hi/lo.
// ---------------------------------------------------------------------------
#define KCH   32
#define NCH   (D_ / KCH)
#define LDKB  80
#define T_A_HI 0
#define T_A_LO 10240
#define T_B_HI 20480
#define T_B_LO 30720
#define STAGE  40960
#define GSMEM  (2 * STAGE)

__device__ __forceinline__ void hmma_gemm_body(
    const __nv_bfloat16* __restrict__ Ahi, const __nv_bfloat16* __restrict__ Alo,
    const __nv_bfloat16* __restrict__ Bhi, const __nv_bfloat16* __restrict__ Blo,
    float* __restrict__ C, const float* __restrict__ bias,
    __nv_bfloat16* __restrict__ Chi, __nv_bfloat16* __restrict__ Clo)
{
    extern __shared__ char sm[];
    const uint32_t sb = smem_u32(sm);
    const int tid  = threadIdx.x;
    const int lane = tid & 31;
    const int wid  = tid >> 5;
    const int wm   = (wid & 1) * 64;
    const int wn   = (wid >> 1) * 32;
    const int m0   = blockIdx.y * 128;
    const int n0   = blockIdx.x * 128;

    const uint32_t aoff = (uint32_t)((wm + (lane & 15)) * LDKB + (lane >> 4) * 16);
    const uint32_t boff = (uint32_t)((wn + (lane & 7))  * LDKB + ((lane >> 3) & 1) * 16);

    float acc[4][4][4];
#pragma unroll
    for (int i = 0; i < 4; i++)
#pragma unroll
        for (int j = 0; j < 4; j++)
#pragma unroll
            for (int q = 0; q < 4; q++) acc[i][j][q] = 0.f;

    auto issue = [&](int c, int s) {
        const int k0 = c * KCH;
        const uint32_t st = sb + s * STAGE;
#pragma unroll
        for (int t = 0; t < 2; t++) {
            int idx = tid + t * 256;
            int row = idx >> 2, q = idx & 3;
            uint32_t so = (uint32_t)(row * LDKB + q * 16);
            const size_t ga = (size_t)(m0 + row) * D_ + k0 + q * 8;
            const size_t gb = (size_t)(n0 + row) * D_ + k0 + q * 8;
            cp16(st + T_A_HI + so, Ahi + ga);
            cp16(st + T_A_LO + so, Alo + ga);
            cp16(st + T_B_HI + so, Bhi + gb);
            cp16(st + T_B_LO + so, Blo + gb);
        }
        CP_COMMIT();
    };

    issue(0, 0);
    for (int c = 0; c < NCH; ++c) {
        const int s = c & 1;
        if (c + 1 < NCH) { issue(c + 1, s ^ 1); CP_WAIT1(); }
        else             { CP_WAIT0(); }
        __syncthreads();

        const uint32_t st = sb + s * STAGE;
        const uint32_t ah_b = st + T_A_HI + aoff;
        const uint32_t al_b = st + T_A_LO + aoff;
        const uint32_t bh_b = st + T_B_HI + boff;
        const uint32_t bl_b = st + T_B_LO + boff;

#pragma unroll
        for (int ks = 0; ks < 2; ks++) {
            const uint32_t ko = ks * 32;
            uint32_t ah[4][4], al[4][4], bh[4][2], bl[4][2];
#pragma unroll
            for (int i = 0; i < 4; i++) {
                ldmA(ah[i], ah_b + ko + i * (16 * LDKB));
                ldmA(al[i], al_b + ko + i * (16 * LDKB));
            }
#pragma unroll
            for (int j = 0; j < 4; j++) {
                ldmB(bh[j], bh_b + ko + j * (8 * LDKB));
                ldmB(bl[j], bl_b + ko + j * (8 * LDKB));
            }
#pragma unroll
            for (int i = 0; i < 4; i++)
#pragma unroll
                for (int j = 0; j < 4; j++) hmma(acc[i][j], ah[i], bh[j]);
#pragma unroll
            for (int i = 0; i < 4; i++)
#pragma unroll
                for (int j = 0; j < 4; j++) hmma(acc[i][j], ah[i], bl[j]);
#pragma unroll
            for (int i = 0; i < 4; i++)
#pragma unroll
                for (int j = 0; j < 4; j++) hmma(acc[i][j], al[i], bh[j]);
        }
        __syncthreads();
    }

    const int gid = lane >> 2, tig = lane & 3;
#pragma unroll
    for (int i = 0; i < 4; i++) {
        const int row = m0 + wm + i * 16 + gid;
#pragma unroll
        for (int j = 0; j < 4; j++) {
            const int col = n0 + wn + j * 8 + tig * 2;
            if (Chi) {
                __nv_bfloat16 h0, l0, h1, l1;
                size_t o0 = (size_t)row * D_ + col;
                size_t o1 = (size_t)(row + 8) * D_ + col;
                split1(acc[i][j][0], h0, l0); split1(acc[i][j][1], h1, l1);
                *(__nv_bfloat162*)(Chi + o0) = __nv_bfloat162(h0, h1);
                *(__nv_bfloat162*)(Clo + o0) = __nv_bfloat162(l0, l1);
                split1(acc[i][j][2], h0, l0); split1(acc[i][j][3], h1, l1);
                *(__nv_bfloat162*)(Chi + o1) = __nv_bfloat162(h0, h1);
                *(__nv_bfloat162*)(Clo + o1) = __nv_bfloat162(l0, l1);
            } else {
                float b0 = bias ? bias[col] : 0.f;
                float b1 = bias ? bias[col + 1] : 0.f;
                *(float2*)(C + (size_t)row * D_ + col) =
                    make_float2(acc[i][j][0] + b0, acc[i][j][1] + b1);
                *(float2*)(C + (size_t)(row + 8) * D_ + col) =
                    make_float2(acc[i][j][2] + b0, acc[i][j][3] + b1);
            }
        }
    }
}

__global__ void __launch_bounds__(256, 1)
hmma_qkv_kernel()
{
    const int z = blockIdx.z;
    __nv_bfloat16* Ch = (z == 0) ? g_qhi : (z == 1) ? g_khi : g_vhi;
    __nv_bfloat16* Cl = (z == 0) ? g_qlo : (z == 1) ? g_klo : g_vlo;
    hmma_gemm_body(g_xhi, g_xlo, g_wThi + (size_t)z * DD, g_wTlo + (size_t)z * DD,
                   nullptr, nullptr, Ch, Cl);
}

__global__ void __launch_bounds__(256, 1)
hmma_out_kernel(const float* __restrict__ bo, float* __restrict__ out)
{
    hmma_gemm_body(g_ahi, g_alo, g_wThi + 3ull * DD, g_wTlo + 3ull * DD,
                   out, bo, nullptr, nullptr);
}

// ---------------------------------------------------------------------------
// HMMA flash attention. CTA = (qb, h, b); 8 warps x 16 q rows.
// KV tiles 64x64, hi/lo bf16, cp.async double buffer, rows padded to 144B.
// S fragments register-reused as P A-fragments.
// ---------------------------------------------------------------------------
#define FQ_HI 0
#define FQ_LO 18432
#define FST   36864          // stages base
#define FSTG  36864          // per-stage size (KH 0, KL 9216, VH 18432, VL 27648)
#define FSMEM (FST + 2 * FSTG)   // 110592
#define QSC   0.1803368801f  // 0.125 * log2(e)

template<bool MASKED>
__device__ __forceinline__ void ftile(
    uint32_t st, int kv0, int row0, int row1, int lane,
    const uint32_t (&qh)[4][4], const uint32_t (&ql)[4][4],
    float& m0, float& m1, float& l0, float& l1, float (&O)[8][4])
{
    const int tig = lane & 3;
    float s[8][4];
#pragma unroll
    for (int j = 0; j < 8; j++)
#pragma unroll
        for (int c = 0; c < 4; c++) s[j][c] = 0.f;

    // S = Qhi@Khi^T + Qlo@Khi^T + Qhi@Klo^T
    const uint32_t kb0 = st + (uint32_t)((lane & 7) * 144 + ((lane >> 3) & 1) * 16);
#pragma unroll
    for (int kk = 0; kk < 4; kk++) {
        const uint32_t kb = kb0 + kk * 32;
#pragma unroll
        for (int j = 0; j < 8; j++) {
            uint32_t kh[2], kl[2];
            ldmB(kh, kb + j * (8 * 144));
            ldmB(kl, kb + 9216 + j * (8 * 144));
            hmma(s[j], qh[kk], kh);
            hmma(s[j], ql[kk], kh);
            hmma(s[j], qh[kk], kl);
        }
    }

    // scale + mask + row max
    float mx0 = -1e30f, mx1 = -1e30f;
#pragma unroll
    for (int j = 0; j < 8; j++) {
#pragma unroll
        for (int c = 0; c < 4; c++) {
            float v = s[j][c] * QSC;
            if (MASKED) {
                int col = kv0 + j * 8 + tig * 2 + (c & 1);
                int row = (c < 2) ? row0 : row1;
                if (col > row) v = -1e30f;
            }
            s[j][c] = v;
            if (c < 2) mx0 = fmaxf(mx0, v); else mx1 = fmaxf(mx1, v);
        }
    }
    mx0 = qmax(mx0); mx1 = qmax(mx1);
    const float m0n = fmaxf(m0, mx0), m1n = fmaxf(m1, mx1);
    const float a0 = ex2(m0 - m0n), a1 = ex2(m1 - m1n);
    m0 = m0n; m1 = m1n;

    float ts0 = 0.f, ts1 = 0.f;
    uint32_t pH[2][8], pL[2][8];
#pragma unroll
    for (int j = 0; j < 8; j++) {
        float p00 = ex2(s[j][0] - m0n), p01 = ex2(s[j][1] - m0n);
        float p10 = ex2(s[j][2] - m1n), p11 = ex2(s[j][3] - m1n);
        if (MASKED) {   // guard fully-masked rows (m == -1e30 -> ex2(0) == 1)
            if (s[j][0] < -1e29f) p00 = 0.f;
            if (s[j][1] < -1e29f) p01 = 0.f;
            if (s[j][2] < -1e29f) p10 = 0.f;
            if (s[j][3] < -1e29f) p11 = 0.f;
        }
        ts0 += p00 + p01; ts1 += p10 + p11;
        float q00 = __bfloat162float(__float2bfloat16(p00));
        float q01 = __bfloat162float(__float2bfloat16(p01));
        float q10 = __bfloat162float(__float2bfloat16(p10));
        float q11 = __bfloat162float(__float2bfloat16(p11));
        pH[0][j] = packbf(p00, p01);
        pH[1][j] = packbf(p10, p11);
        pL[0][j] = packbf(p00 - q00, p01 - q01);
        pL[1][j] = packbf(p10 - q10, p11 - q11);
    }
    ts0 = qsum(ts0); ts1 = qsum(ts1);
    l0 = l0 * a0 + ts0;
    l1 = l1 * a1 + ts1;
#pragma unroll
    for (int j = 0; j < 8; j++) {
        O[j][0] *= a0; O[j][1] *= a0; O[j][2] *= a1; O[j][3] *= a1;
    }

    // O += Phi@Vhi + Phi@Vlo + Plo@Vhi   (V via ldmatrix.trans)
#pragma unroll
    for (int kk = 0; kk < 4; kk++) {
        uint32_t ah[4] = { pH[0][2 * kk], pH[1][2 * kk],
                           pH[0][2 * kk + 1], pH[1][2 * kk + 1] };
        uint32_t al[4] = { pL[0][2 * kk], pL[1][2 * kk],
                           pL[0][2 * kk + 1], pL[1][2 * kk + 1] };
        const uint32_t vb = st + 18432
            + (uint32_t)((kk * 16 + (lane & 7) + ((lane >> 3) & 1) * 8) * 144);
#pragma unroll
        for (int j = 0; j < 8; j++) {
            uint32_t vh[2], vl[2];
            ldmBT(vh, vb + j * 16);
            ldmBT(vl, vb + 9216 + j * 16);
            hmma(O[j], ah, vh);
            hmma(O[j], ah, vl);
            hmma(O[j], al, vh);
        }
    }
}

__global__ void __launch_bounds__(256)
flash_hmma_kernel()
{
    extern __shared__ char fsm[];
    const uint32_t sb = smem_u32(fsm);
    const int tid = threadIdx.x, lane = tid & 31, wid = tid >> 5;
    const int qb = gridDim.x - 1 - blockIdx.x;   // big tiles first
    const int h = blockIdx.y, b = blockIdx.z;
    const int ntiles = qb * 2 + 2;

    auto issueT = [&](int t, int s) {
        const uint32_t st = sb + FST + s * FSTG;
        const int kv0 = t * 64;
#pragma unroll
        for (int i = 0; i < 2; i++) {
            int c = tid + i * 256;
            int row = c >> 3, q = c & 7;
            size_t g = (size_t)(b * S_ + kv0 + row) * D_ + h * HD_ + q * 8;
            uint32_t so = (uint32_t)(row * 144 + q * 16);
            cp16(st + so,         g_khi + g);
            cp16(st + 9216 + so,  g_klo + g);
            cp16(st + 18432 + so, g_vhi + g);
            cp16(st + 27648 + so, g_vlo + g);
        }
        CP_COMMIT();
    };

    // Q + tile0 (group 0), tile1 (group 1)
    {
#pragma unroll
        for (int i = 0; i < 4; i++) {
            int c = tid + i * 256;
            int row = c >> 3, q = c & 7;
            size_t g = (size_t)(b * S_ + qb * 128 + row) * D_ + h * HD_ + q * 8;
            uint32_t so = (uint32_t)(row * 144 + q * 16);
            cp16(sb + FQ_HI + so, g_qhi + g);
            cp16(sb + FQ_LO + so, g_qlo + g);
        }
        const uint32_t st = sb + FST;
#pragma unroll
        for (int i = 0; i < 2; i++) {
            int c = tid + i * 256;
            int row = c >> 3, q = c & 7;
            size_t g = (size_t)(b * S_ + row) * D_ + h * HD_ + q * 8;
            uint32_t so = (uint32_t)(row * 144 + q * 16);
            cp16(st + so,         g_khi + g);
            cp16(st + 9216 + so,  g_klo + g);
            cp16(st + 18432 + so, g_vhi + g);
            cp16(st + 27648 + so, g_vlo + g);
        }
        CP_COMMIT();
        issueT(1, 1);
    }

    const int gid = lane >> 2;
    const int q0w = qb * 128 + wid * 16;
    const int row0 = q0w + gid, row1 = row0 + 8;
    float m0 = -1e30f, m1 = -1e30f, l0 = 0.f, l1 = 0.f;
    float O[8][4];
#pragma unroll
    for (int j = 0; j < 8; j++)
#pragma unroll
        for (int c = 0; c < 4; c++) O[j][c] = 0.f;
    uint32_t qh[4][4], ql[4][4];
    bool qloaded = false;

    for (int t = 0; t < ntiles; t++) {
        if (t + 1 < ntiles) CP_WAIT1(); else CP_WAIT0();
        __syncthreads();
        if (!qloaded) {
            const uint32_t qa = (uint32_t)((wid * 16 + (lane & 15)) * 144
                                           + (lane >> 4) * 16);
#pragma unroll
            for (int kk = 0; kk < 4; kk++) {
                ldmA(qh[kk], sb + FQ_HI + qa + kk * 32);
                ldmA(ql[kk], sb + FQ_LO + qa + kk * 32);
            }
            qloaded = true;
        }
        const uint32_t st = sb + FST + (t & 1) * FSTG;
        const int kv0 = t * 64;
        if (q0w + 15 >= kv0) {
            if (kv0 + 63 > q0w)
                ftile<true >(st, kv0, row0, row1, lane, qh, ql, m0, m1, l0, l1, O);
            else
                ftile<false>(st, kv0, row0, row1, lane, qh, ql, m0, m1, l0, l1, O);
        }
        __syncthreads();
        if (t + 2 < ntiles) issueT(t + 2, t & 1);
    }

    // epilogue: normalize, split hi/lo, write mis-reshaped layout
    const float inv0 = 1.f / l0, inv1 = 1.f / l1;
    const int tig = lane & 3;
#pragma unroll
    for (int j = 0; j < 8; j++) {
        const int d = j * 8 + tig * 2;
        size_t o0 = (size_t)(b * S_ + h * 128 + (row0 >> 4)) * D_ + (row0 & 15) * 64 + d;
        size_t o1 = (size_t)(b * S_ + h * 128 + (row1 >> 4)) * D_ + (row1 & 15) * 64 + d;
        __nv_bfloat16 h0, lo0, h1, lo1;
        split1(O[j][0] * inv0, h0, lo0); split1(O[j][1] * inv0, h1, lo1);
        *(__nv_bfloat162*)(g_ahi + o0) = __nv_bfloat162(h0, h1);
        *(__nv_bfloat162*)(g_alo + o0) = __nv_bfloat162(lo0, lo1);
        split1(O[j][2] * inv1, h0, lo0); split1(O[j][3] * inv1, h1, lo1);
        *(__nv_bfloat162*)(g_ahi + o1) = __nv_bfloat162(h0, h1);
        *(__nv_bfloat162*)(g_alo + o1) = __nv_bfloat162(lo0, lo1);
    }
}

// ---------------------------------------------------------------------------
// Launch
// ---------------------------------------------------------------------------
extern "C" void kernel_launch(void* const* d_in, const int* in_sizes, int n_in,
                              void* d_out, int out_size)
{
    const float* x  = (const float*)d_in[0];
    const float* Wq = (const float*)d_in[1];
    const float* Wk = (const float*)d_in[2];
    const float* Wv = (const float*)d_in[3];
    const float* Wo = (const float*)d_in[4];
    const float* bo = (const float*)d_in[5];
    float* out = (float*)d_out;

    cudaFuncSetAttribute(hmma_qkv_kernel,
                         cudaFuncAttributeMaxDynamicSharedMemorySize, GSMEM);
    cudaFuncSetAttribute(hmma_out_kernel,
                         cudaFuncAttributeMaxDynamicSharedMemorySize, GSMEM);
    cudaFuncSetAttribute(flash_hmma_kernel,
                         cudaFuncAttributeMaxDynamicSharedMemorySize, FSMEM);

    const int n4 = MTOT * D_ / 4;

    conv_x_kernel<<<n4 / 256, 256>>>(x);
    conv_wT_kernel<<<dim3(32, 32, 4), 256>>>(Wq, Wk, Wv, Wo);

    hmma_qkv_kernel<<<dim3(D_ / 128, MTOT / 128, 3), 256, GSMEM>>>();

    flash_hmma_kernel<<<dim3(S_ / 128, H_, B_), 256, FSMEM>>>();

    hmma_out_kernel<<<dim3(D_ / 128, MTOT / 128, 1), 256, GSMEM>>>(bo, out);
}